// round 10
// baseline (speedup 1.0000x reference)
#include <cuda_runtime.h>
#include <cuda_fp16.h>
#include <cstdint>

#define SEQ 8192
#define DIM 512
#define DK  64
#define DV  64
#define BM  128
#define BN  64
#define NSPLIT 8
#define KV_PER (SEQ/NSPLIT)     // 1024
#define TILES  (KV_PER/BN)      // 16

// ---- flash smem (bytes): stride 144 everywhere ----
#define FS 144
#define FK_TB (64 * FS)              // 9216
#define SM_QH 0                      // 128 rows * 144 = 18432
#define SM_QL 18432
#define SM_KH 36864                  // 2 bufs * 9216
#define SM_KL (36864 + 18432)        // 55296
#define SM_V  (55296 + 18432)        // 73728, 2 bufs
#define SM_TOTAL (73728 + 18432)     // 92160

// ---- qkv smem (bytes): M-tile 64, k-chunk 64, stride 144 ----
#define QS 144
#define QK_TB (64 * QS)             // 9216 per split tile
#define QK_BUF (4 * QK_TB)          // xh, xl, wh, wl = 36864
#define QK_SMEM (2 * QK_BUF)        // 73728

// ---------------- global scratch ----------------
__device__ __half g_xh[SEQ*DIM], g_xl[SEQ*DIM];
__device__ __half g_Wth[3*DK*DIM], g_Wtl[3*DK*DIM];  // W^T [n][k], Q pre-scaled
__device__ __half g_Qh[SEQ*DK], g_Ql[SEQ*DK];
__device__ __half g_Kh[SEQ*DK], g_Kl[SEQ*DK];
__device__ __half g_Vht[DV*SEQ];                     // V^T fp16
__device__ float  g_Op[NSPLIT*SEQ*DV];
__device__ float  g_pm[NSPLIT*SEQ], g_pl[NSPLIT*SEQ];

// ---------------- helpers ----------------
__device__ __forceinline__ uint32_t smem_u32(const void* p){
    uint32_t a;
    asm("{ .reg .u64 t; cvta.to.shared.u64 t, %1; cvt.u32.u64 %0, t; }" : "=r"(a) : "l"(p));
    return a;
}
#define CP16(dst, src) asm volatile("cp.async.cg.shared.global [%0], [%1], 16;" :: "r"(dst), "l"(src) : "memory")
#define CP_COMMIT()    asm volatile("cp.async.commit_group;" ::: "memory")
#define CP_WAIT0()     asm volatile("cp.async.wait_group 0;" ::: "memory")

__device__ __forceinline__ void mma16816(float* c, const uint32_t* a, uint32_t b0, uint32_t b1){
    asm volatile("mma.sync.aligned.m16n8k16.row.col.f32.f16.f16.f32 "
        "{%0,%1,%2,%3}, {%4,%5,%6,%7}, {%8,%9}, {%0,%1,%2,%3};"
        : "+f"(c[0]), "+f"(c[1]), "+f"(c[2]), "+f"(c[3])
        : "r"(a[0]), "r"(a[1]), "r"(a[2]), "r"(a[3]), "r"(b0), "r"(b1));
}
__device__ __forceinline__ void ldsm4(uint32_t* r, uint32_t addr){
    asm volatile("ldmatrix.sync.aligned.m8n8.x4.shared.b16 {%0,%1,%2,%3}, [%4];"
        : "=r"(r[0]), "=r"(r[1]), "=r"(r[2]), "=r"(r[3]) : "r"(addr));
}
__device__ __forceinline__ uint32_t packh2(float lo, float hi){
    __half2 h = __floats2half2_rn(lo, hi);
    return reinterpret_cast<uint32_t&>(h);
}

// ---------------------------------------------------------------------------
// Converts
// ---------------------------------------------------------------------------
__global__ __launch_bounds__(256, 1) void convert_x(const float* __restrict__ x)
{
    size_t i = ((size_t)blockIdx.x * 256 + threadIdx.x) * 4;
    float4 v = *(const float4*)(x + i);
    __half h0 = __float2half_rn(v.x), h1 = __float2half_rn(v.y);
    __half h2 = __float2half_rn(v.z), h3 = __float2half_rn(v.w);
    *(__half2*)&g_xh[i]   = __halves2half2(h0, h1);
    *(__half2*)&g_xh[i+2] = __halves2half2(h2, h3);
    *(__half2*)&g_xl[i]   = __floats2half2_rn(v.x - __half2float(h0), v.y - __half2float(h1));
    *(__half2*)&g_xl[i+2] = __floats2half2_rn(v.z - __half2float(h2), v.w - __half2float(h3));
}

__global__ __launch_bounds__(256, 1) void convert_w(
    const float* __restrict__ Wq, const float* __restrict__ Wk, const float* __restrict__ Wv)
{
    const int w = blockIdx.x;
    const float* W = (w == 0) ? Wq : (w == 1) ? Wk : Wv;
    const float sc = (w == 0) ? 0.125f : 1.0f;     // fold 1/sqrt(64) into Wq
    __half* Hh = g_Wth + (size_t)w * DK * DIM;
    __half* Hl = g_Wtl + (size_t)w * DK * DIM;
    int idx = blockIdx.y * 4096 + threadIdx.x;
    #pragma unroll
    for (int i = 0; i < 16; i++, idx += 256) {
        int k = idx / DK, n = idx % DK;
        float v = W[idx] * sc;
        __half h = __float2half_rn(v);
        Hh[(size_t)n * DIM + k] = h;
        Hl[(size_t)n * DIM + k] = __float2half_rn(v - __half2float(h));
    }
}

// ---------------------------------------------------------------------------
// HMMA QKV: C = x @ W, 3-term fp16 split. grid (SEQ/64, 3), 256 thr.
// ---------------------------------------------------------------------------
__global__ __launch_bounds__(256, 1) void hmma_qkv()
{
    extern __shared__ char smem[];
    const uint32_t sb = smem_u32(smem);
    const int tid = threadIdx.x, wid = tid >> 5, lane = tid & 31;
    const int g = lane >> 2, tig = lane & 3;
    const int mw = wid & 3;
    const int nw = wid >> 2;
    const int which = blockIdx.y;
    const int m0 = blockIdx.x * 64;
    const __half* Wh = g_Wth + (size_t)which * DK * DIM;
    const __half* Wl = g_Wtl + (size_t)which * DK * DIM;

    auto load_chunk = [&](int buf, int k0) {
        uint32_t base = sb + buf * QK_BUF;
        #pragma unroll
        for (int i = 0; i < 2; i++) {
            int f = i * 256 + tid;
            int row = f >> 3, c = f & 7;
            uint32_t d = (uint32_t)(row * QS + c * 16);
            const size_t s = (size_t)(m0 + row) * DIM + k0 + c * 8;
            CP16(base + d,         g_xh + s);
            CP16(base + QK_TB + d, g_xl + s);
        }
        #pragma unroll
        for (int i = 0; i < 2; i++) {
            int f = i * 256 + tid;
            int row = f >> 3, c = f & 7;
            uint32_t d = (uint32_t)(row * QS + c * 16);
            const size_t s = (size_t)row * DIM + k0 + c * 8;
            CP16(base + 2*QK_TB + d, Wh + s);
            CP16(base + 3*QK_TB + d, Wl + s);
        }
    };

    load_chunk(0, 0);
    CP_COMMIT();

    float c[4][4];
    #pragma unroll
    for (int nt = 0; nt < 4; nt++)
        c[nt][0] = c[nt][1] = c[nt][2] = c[nt][3] = 0.0f;

    for (int ch = 0; ch < 8; ch++) {
        CP_WAIT0();
        __syncthreads();
        if (ch < 7) { load_chunk((ch + 1) & 1, (ch + 1) * 64); CP_COMMIT(); }

        const uint32_t xb = sb + (ch & 1) * QK_BUF;

        uint32_t ah[4][4], al[4][4];
        #pragma unroll
        for (int ks = 0; ks < 4; ks++) {
            uint32_t aoff = (uint32_t)((mw * 16 + (lane & 15)) * QS
                                       + ks * 32 + (lane >> 4) * 16);
            ldsm4(ah[ks], xb + aoff);
            ldsm4(al[ks], xb + QK_TB + aoff);
        }
        #pragma unroll
        for (int nt = 0; nt < 4; nt++) {
            #pragma unroll
            for (int kp = 0; kp < 2; kp++) {
                uint32_t woff = (uint32_t)((nw * 32 + nt * 8 + (lane & 7)) * QS
                                           + kp * 64 + (lane >> 3) * 16);
                uint32_t wh[4], wl[4];
                ldsm4(wh, xb + 2*QK_TB + woff);
                ldsm4(wl, xb + 3*QK_TB + woff);
                #pragma unroll
                for (int s = 0; s < 2; s++) {
                    int ks = kp * 2 + s;
                    mma16816(c[nt], ah[ks], wh[2*s], wh[2*s+1]);
                    mma16816(c[nt], ah[ks], wl[2*s], wl[2*s+1]);
                    mma16816(c[nt], al[ks], wh[2*s], wh[2*s+1]);
                }
            }
        }
    }

    if (which == 2) {
        #pragma unroll
        for (int nt = 0; nt < 4; nt++)
            #pragma unroll
            for (int h = 0; h < 2; h++) {
                int row = m0 + mw * 16 + g + 8 * h;
                int col = nw * 32 + nt * 8 + 2 * tig;
                g_Vht[(size_t)col * SEQ + row]       = __float2half_rn(c[nt][2*h]);
                g_Vht[(size_t)(col + 1) * SEQ + row] = __float2half_rn(c[nt][2*h+1]);
            }
    } else {
        __half* Hp = which ? g_Kh : g_Qh;
        __half* Lp = which ? g_Kl : g_Ql;
        #pragma unroll
        for (int nt = 0; nt < 4; nt++)
            #pragma unroll
            for (int h = 0; h < 2; h++) {
                int row = m0 + mw * 16 + g + 8 * h;
                float v0 = c[nt][2*h], v1 = c[nt][2*h+1];
                __half h0 = __float2half_rn(v0), h1 = __float2half_rn(v1);
                size_t base = (size_t)row * DK + nw * 32 + nt * 8 + 2 * tig;
                *(__half2*)&Hp[base] = __halves2half2(h0, h1);
                *(__half2*)&Lp[base] = __floats2half2_rn(v0 - __half2float(h0),
                                                         v1 - __half2float(h1));
            }
    }
}

// ---------------------------------------------------------------------------
// flash smem loaders (stride 144; 64-row tiles = 512 chunks = 2 iters)
// ---------------------------------------------------------------------------
__device__ __forceinline__ void load_k64(uint32_t dstbase, const __half* src, int n0, int tid){
    #pragma unroll
    for (int i = 0; i < 2; i++) {
        int f = i * 256 + tid;
        int row = f >> 3, c = f & 7;
        CP16(dstbase + (uint32_t)(row * FS + c * 16),
             src + (size_t)(n0 + row) * DK + c * 8);
    }
}
__device__ __forceinline__ void load_v64(uint32_t dstbase, const __half* src, int k0, int tid){
    #pragma unroll
    for (int i = 0; i < 2; i++) {
        int f = i * 256 + tid;
        int row = f >> 3, c = f & 7;
        CP16(dstbase + (uint32_t)(row * FS + c * 16),
             src + (size_t)row * SEQ + k0 + c * 8);
    }
}

// ---------------------------------------------------------------------------
// HMMA flash attention. grid = (SEQ/BM, NSPLIT) = (64, 8), 256 threads.
// 512 CTAs stream through 296 residency slots -> hardware load balancing.
// ---------------------------------------------------------------------------
__global__ __launch_bounds__(256, 2) void flash_kernel()
{
    extern __shared__ char smem[];
    const uint32_t sb = smem_u32(smem);

    const int tid  = threadIdx.x;
    const int wid  = tid >> 5;
    const int lane = tid & 31;
    const int g    = lane >> 2;
    const int tig  = lane & 3;
    const int q0   = blockIdx.x * BM;
    const int split  = blockIdx.y;
    const int n_base = split * KV_PER;

    // prologue: Q (h+l) into smem + KV tile 0 into buf 0
    #pragma unroll
    for (int i = 0; i < 4; i++) {                 // Qh: 128 rows * 8 chunks
        int f = i * 256 + tid;
        int row = f >> 3, c = f & 7;
        uint32_t d = (uint32_t)(row * FS + c * 16);
        const size_t s = (size_t)(q0 + row) * DK + c * 8;
        CP16(sb + SM_QH + d, g_Qh + s);
        CP16(sb + SM_QL + d, g_Ql + s);
    }
    load_k64(sb + SM_KH, g_Kh, n_base, tid);
    load_k64(sb + SM_KL, g_Kl, n_base, tid);
    load_v64(sb + SM_V,  g_Vht, n_base, tid);
    CP_COMMIT();

    float O[8][4];
    #pragma unroll
    for (int d = 0; d < 8; d++)
        #pragma unroll
        for (int j = 0; j < 4; j++) O[d][j] = 0.0f;
    float m_run[2] = {-1e30f, -1e30f};
    float l_run[2] = {0.0f, 0.0f};

    for (int t = 0; t < TILES; ++t) {
        CP_WAIT0();
        __syncthreads();

        const int buf = t & 1, nb = (t + 1) & 1;
        if (t + 1 < TILES) {
            int n1 = n_base + (t + 1) * BN;
            load_k64(sb + SM_KH + nb * FK_TB, g_Kh, n1, tid);
            load_k64(sb + SM_KL + nb * FK_TB, g_Kl, n1, tid);
            load_v64(sb + SM_V  + nb * FK_TB, g_Vht, n1, tid);
        }
        CP_COMMIT();

        // Q A-fragments reloaded from smem (keeps them transient)
        uint32_t aQh[4][4], aQl[4][4];
        #pragma unroll
        for (int ks = 0; ks < 4; ks++) {
            uint32_t aoff = (uint32_t)((wid * 16 + (lane & 15)) * FS
                                       + ks * 32 + (lane >> 4) * 16);
            ldsm4(aQh[ks], sb + SM_QH + aoff);
            ldsm4(aQl[ks], sb + SM_QL + aoff);
        }

        // S = Qh*Kh + Qh*Kl + Ql*Kh   (16 x 64 per warp)
        const uint32_t khb = sb + SM_KH + buf * FK_TB;
        const uint32_t klb = sb + SM_KL + buf * FK_TB;
        float c[8][4];
        #pragma unroll
        for (int nt = 0; nt < 8; nt++) {
            c[nt][0] = c[nt][1] = c[nt][2] = c[nt][3] = 0.0f;
            #pragma unroll
            for (int kp = 0; kp < 2; kp++) {
                uint32_t off = (uint32_t)((nt * 8 + (lane & 7)) * FS
                                          + kp * 64 + (lane >> 3) * 16);
                uint32_t bh[4], bl[4];
                ldsm4(bh, khb + off);
                ldsm4(bl, klb + off);
                #pragma unroll
                for (int s = 0; s < 2; s++) {
                    int ks = kp * 2 + s;
                    mma16816(c[nt], aQh[ks], bh[2*s], bh[2*s+1]);
                    mma16816(c[nt], aQh[ks], bl[2*s], bl[2*s+1]);
                    mma16816(c[nt], aQl[ks], bh[2*s], bh[2*s+1]);
                }
            }
        }

        // online softmax (warp-local; rows g and g+8)
        #pragma unroll
        for (int h = 0; h < 2; h++) {
            float mt = -1e30f;
            #pragma unroll
            for (int nt = 0; nt < 8; nt++)
                mt = fmaxf(mt, fmaxf(c[nt][2*h], c[nt][2*h+1]));
            mt = fmaxf(mt, __shfl_xor_sync(0xffffffffu, mt, 1));
            mt = fmaxf(mt, __shfl_xor_sync(0xffffffffu, mt, 2));
            float mnew  = fmaxf(m_run[h], mt);
            float alpha = __expf(m_run[h] - mnew);
            float sum = 0.0f;
            #pragma unroll
            for (int nt = 0; nt < 8; nt++) {
                float e0 = __expf(c[nt][2*h]   - mnew);
                float e1 = __expf(c[nt][2*h+1] - mnew);
                c[nt][2*h] = e0; c[nt][2*h+1] = e1;
                sum += e0 + e1;
            }
            sum += __shfl_xor_sync(0xffffffffu, sum, 1);
            sum += __shfl_xor_sync(0xffffffffu, sum, 2);
            m_run[h] = mnew;
            l_run[h] = l_run[h] * alpha + sum;
            #pragma unroll
            for (int d = 0; d < 8; d++) { O[d][2*h] *= alpha; O[d][2*h+1] *= alpha; }
        }

        // pack P (S-frag -> A-frag reuse): 4 k-tiles of 16 kv
        uint32_t aP[4][4];
        #pragma unroll
        for (int k2 = 0; k2 < 4; k2++) {
            aP[k2][0] = packh2(c[2*k2][0],   c[2*k2][1]);
            aP[k2][1] = packh2(c[2*k2][2],   c[2*k2][3]);
            aP[k2][2] = packh2(c[2*k2+1][0], c[2*k2+1][1]);
            aP[k2][3] = packh2(c[2*k2+1][2], c[2*k2+1][3]);
        }

        // O += P @ Vh
        const uint32_t vhb = sb + SM_V + buf * FK_TB;
        #pragma unroll
        for (int dt = 0; dt < 8; dt++) {
            #pragma unroll
            for (int vp = 0; vp < 2; vp++) {
                uint32_t off = (uint32_t)((dt * 8 + (lane & 7)) * FS
                                          + vp * 64 + (lane >> 3) * 16);
                uint32_t vh[4];
                ldsm4(vh, vhb + off);
                #pragma unroll
                for (int s = 0; s < 2; s++) {
                    int k2 = vp * 2 + s;
                    mma16816(O[dt], aP[k2], vh[2*s], vh[2*s+1]);
                }
            }
        }
    }

    // epilogue: unnormalized partials + (m, l)
    #pragma unroll
    for (int h = 0; h < 2; h++) {
        int row = q0 + wid * 16 + g + 8 * h;
        size_t rb = ((size_t)split * SEQ + row) * DV;
        #pragma unroll
        for (int dt = 0; dt < 8; dt++) {
            float2 v = make_float2(O[dt][2*h], O[dt][2*h+1]);
            *(float2*)&g_Op[rb + dt * 8 + 2 * tig] = v;
        }
        if (tig == 0) {
            g_pm[split * SEQ + row] = m_run[h];
            g_pl[split * SEQ + row] = l_run[h];
        }
    }
}

// ---------------------------------------------------------------------------
// combine the NSPLIT KV-split partials
// ---------------------------------------------------------------------------
__global__ __launch_bounds__(256, 1) void combine_kernel(float* __restrict__ out)
{
    int idx = blockIdx.x * 256 + threadIdx.x;
    int row = idx >> 4;
    int c4  = (idx & 15) * 4;

    float m[NSPLIT];
    float M = -1e30f;
    #pragma unroll
    for (int j = 0; j < NSPLIT; j++) {
        m[j] = g_pm[j * SEQ + row];
        M = fmaxf(M, m[j]);
    }
    float w[NSPLIT];
    float l = 0.0f;
    #pragma unroll
    for (int j = 0; j < NSPLIT; j++) {
        w[j] = __expf(m[j] - M);
        l += w[j] * g_pl[j * SEQ + row];
    }
    float inv = 1.0f / l;

    float4 o = make_float4(0.f, 0.f, 0.f, 0.f);
    #pragma unroll
    for (int j = 0; j < NSPLIT; j++) {
        float4 a = *(const float4*)&g_Op[((size_t)j * SEQ + row) * DV + c4];
        o.x += w[j] * a.x; o.y += w[j] * a.y;
        o.z += w[j] * a.z; o.w += w[j] * a.w;
    }
    o.x *= inv; o.y *= inv; o.z *= inv; o.w *= inv;
    *(float4*)&out[(size_t)row * DV + c4] = o;
}

// ---------------------------------------------------------------------------
extern "C" void kernel_launch(void* const* d_in, const int* in_sizes, int n_in,
                              void* d_out, int out_size)
{
    const float* x  = (const float*)d_in[0];
    const float* Wq = (const float*)d_in[1];
    const float* Wk = (const float*)d_in[2];
    const float* Wv = (const float*)d_in[3];
    float* out = (float*)d_out;

    convert_x<<<SEQ * DIM / 1024, 256>>>(x);
    convert_w<<<dim3(3, 8), 256>>>(Wq, Wk, Wv);

    cudaFuncSetAttribute(hmma_qkv,
                         cudaFuncAttributeMaxDynamicSharedMemorySize, QK_SMEM);
    hmma_qkv<<<dim3(SEQ / 64, 3), 256, QK_SMEM>>>();

    cudaFuncSetAttribute(flash_kernel,
                         cudaFuncAttributeMaxDynamicSharedMemorySize, SM_TOTAL);
    flash_kernel<<<dim3(SEQ / BM, NSPLIT), 256, SM_TOTAL>>>();

    combine_kernel<<<SEQ * 16 / 256, 256>>>(out);
}

// round 11
// speedup vs baseline: 1.0269x; 1.0269x over previous
#include <cuda_runtime.h>
#include <cuda_fp16.h>
#include <cstdint>

#define SEQ 8192
#define DIM 512
#define DK  64
#define DV  64
#define BM  128
#define BN  64
#define NSPLIT 4
#define KV_PER (SEQ/NSPLIT)     // 2048
#define TILES  (KV_PER/BN)      // 32

// ---- flash smem (bytes): stride 144 everywhere ----
#define FS 144
#define FK_TB (64 * FS)              // 9216
#define SM_QH 0                      // 128 rows * 144 = 18432
#define SM_QL 18432
#define SM_KH 36864                  // 2 bufs * 9216
#define SM_KL (36864 + 18432)        // 55296
#define SM_V  (55296 + 18432)        // 73728, 2 bufs
#define SM_TOTAL (73728 + 18432)     // 92160

// ---- qkv smem (bytes): M-tile 64, k-chunk 64, stride 144 ----
#define QS 144
#define QK_TB (64 * QS)             // 9216 per split tile
#define QK_BUF (4 * QK_TB)          // xh, xl, wh, wl = 36864
#define QK_SMEM (2 * QK_BUF)        // 73728

#define L2E 1.4426950408889634f

// ---------------- global scratch ----------------
__device__ __half g_xh[SEQ*DIM], g_xl[SEQ*DIM];
__device__ __half g_Wth[3*DK*DIM], g_Wtl[3*DK*DIM];  // W^T [n][k], Q pre-scaled
__device__ __half g_Qh[SEQ*DK], g_Ql[SEQ*DK];
__device__ __half g_Kh[SEQ*DK], g_Kl[SEQ*DK];
__device__ __half g_Vht[DV*SEQ];                     // V^T fp16
__device__ float  g_Op[NSPLIT*SEQ*DV];
__device__ float  g_pm[NSPLIT*SEQ], g_pl[NSPLIT*SEQ];

// ---------------- helpers ----------------
__device__ __forceinline__ uint32_t smem_u32(const void* p){
    uint32_t a;
    asm("{ .reg .u64 t; cvta.to.shared.u64 t, %1; cvt.u32.u64 %0, t; }" : "=r"(a) : "l"(p));
    return a;
}
#define CP16(dst, src) asm volatile("cp.async.cg.shared.global [%0], [%1], 16;" :: "r"(dst), "l"(src) : "memory")
#define CP_COMMIT()    asm volatile("cp.async.commit_group;" ::: "memory")
#define CP_WAIT0()     asm volatile("cp.async.wait_group 0;" ::: "memory")

__device__ __forceinline__ void mma16816(float* c, const uint32_t* a, uint32_t b0, uint32_t b1){
    asm volatile("mma.sync.aligned.m16n8k16.row.col.f32.f16.f16.f32 "
        "{%0,%1,%2,%3}, {%4,%5,%6,%7}, {%8,%9}, {%0,%1,%2,%3};"
        : "+f"(c[0]), "+f"(c[1]), "+f"(c[2]), "+f"(c[3])
        : "r"(a[0]), "r"(a[1]), "r"(a[2]), "r"(a[3]), "r"(b0), "r"(b1));
}
__device__ __forceinline__ void ldsm4(uint32_t* r, uint32_t addr){
    asm volatile("ldmatrix.sync.aligned.m8n8.x4.shared.b16 {%0,%1,%2,%3}, [%4];"
        : "=r"(r[0]), "=r"(r[1]), "=r"(r[2]), "=r"(r[3]) : "r"(addr));
}
// pack two fp32 exponents (base-2) to half2 and exponentiate on MUFU.f16x2
__device__ __forceinline__ uint32_t ex2h2(float lo, float hi){
    __half2 h = __floats2half2_rn(lo, hi);
    uint32_t u = reinterpret_cast<uint32_t&>(h);
    uint32_t r;
    asm volatile("ex2.approx.f16x2 %0, %1;" : "=r"(r) : "r"(u));
    return r;
}

// ---------------------------------------------------------------------------
// Converts
// ---------------------------------------------------------------------------
__global__ __launch_bounds__(256, 1) void convert_x(const float* __restrict__ x)
{
    size_t i = ((size_t)blockIdx.x * 256 + threadIdx.x) * 4;
    float4 v = *(const float4*)(x + i);
    __half h0 = __float2half_rn(v.x), h1 = __float2half_rn(v.y);
    __half h2 = __float2half_rn(v.z), h3 = __float2half_rn(v.w);
    *(__half2*)&g_xh[i]   = __halves2half2(h0, h1);
    *(__half2*)&g_xh[i+2] = __halves2half2(h2, h3);
    *(__half2*)&g_xl[i]   = __floats2half2_rn(v.x - __half2float(h0), v.y - __half2float(h1));
    *(__half2*)&g_xl[i+2] = __floats2half2_rn(v.z - __half2float(h2), v.w - __half2float(h3));
}

__global__ __launch_bounds__(256, 1) void convert_w(
    const float* __restrict__ Wq, const float* __restrict__ Wk, const float* __restrict__ Wv)
{
    const int w = blockIdx.x;
    const float* W = (w == 0) ? Wq : (w == 1) ? Wk : Wv;
    const float sc = (w == 0) ? 0.125f : 1.0f;     // fold 1/sqrt(64) into Wq
    __half* Hh = g_Wth + (size_t)w * DK * DIM;
    __half* Hl = g_Wtl + (size_t)w * DK * DIM;
    int idx = blockIdx.y * 4096 + threadIdx.x;
    #pragma unroll
    for (int i = 0; i < 16; i++, idx += 256) {
        int k = idx / DK, n = idx % DK;
        float v = W[idx] * sc;
        __half h = __float2half_rn(v);
        Hh[(size_t)n * DIM + k] = h;
        Hl[(size_t)n * DIM + k] = __float2half_rn(v - __half2float(h));
    }
}

// ---------------------------------------------------------------------------
// HMMA QKV: C = x @ W, 3-term fp16 split. grid (SEQ/64, 3), 256 thr.
// ---------------------------------------------------------------------------
__global__ __launch_bounds__(256, 1) void hmma_qkv()
{
    extern __shared__ char smem[];
    const uint32_t sb = smem_u32(smem);
    const int tid = threadIdx.x, wid = tid >> 5, lane = tid & 31;
    const int g = lane >> 2, tig = lane & 3;
    const int mw = wid & 3;
    const int nw = wid >> 2;
    const int which = blockIdx.y;
    const int m0 = blockIdx.x * 64;
    const __half* Wh = g_Wth + (size_t)which * DK * DIM;
    const __half* Wl = g_Wtl + (size_t)which * DK * DIM;

    auto load_chunk = [&](int buf, int k0) {
        uint32_t base = sb + buf * QK_BUF;
        #pragma unroll
        for (int i = 0; i < 2; i++) {
            int f = i * 256 + tid;
            int row = f >> 3, c = f & 7;
            uint32_t d = (uint32_t)(row * QS + c * 16);
            const size_t s = (size_t)(m0 + row) * DIM + k0 + c * 8;
            CP16(base + d,         g_xh + s);
            CP16(base + QK_TB + d, g_xl + s);
        }
        #pragma unroll
        for (int i = 0; i < 2; i++) {
            int f = i * 256 + tid;
            int row = f >> 3, c = f & 7;
            uint32_t d = (uint32_t)(row * QS + c * 16);
            const size_t s = (size_t)row * DIM + k0 + c * 8;
            CP16(base + 2*QK_TB + d, Wh + s);
            CP16(base + 3*QK_TB + d, Wl + s);
        }
    };

    load_chunk(0, 0);
    CP_COMMIT();

    float c[4][4];
    #pragma unroll
    for (int nt = 0; nt < 4; nt++)
        c[nt][0] = c[nt][1] = c[nt][2] = c[nt][3] = 0.0f;

    for (int ch = 0; ch < 8; ch++) {
        CP_WAIT0();
        __syncthreads();
        if (ch < 7) { load_chunk((ch + 1) & 1, (ch + 1) * 64); CP_COMMIT(); }

        const uint32_t xb = sb + (ch & 1) * QK_BUF;

        uint32_t ah[4][4], al[4][4];
        #pragma unroll
        for (int ks = 0; ks < 4; ks++) {
            uint32_t aoff = (uint32_t)((mw * 16 + (lane & 15)) * QS
                                       + ks * 32 + (lane >> 4) * 16);
            ldsm4(ah[ks], xb + aoff);
            ldsm4(al[ks], xb + QK_TB + aoff);
        }
        #pragma unroll
        for (int nt = 0; nt < 4; nt++) {
            #pragma unroll
            for (int kp = 0; kp < 2; kp++) {
                uint32_t woff = (uint32_t)((nw * 32 + nt * 8 + (lane & 7)) * QS
                                           + kp * 64 + (lane >> 3) * 16);
                uint32_t wh[4], wl[4];
                ldsm4(wh, xb + 2*QK_TB + woff);
                ldsm4(wl, xb + 3*QK_TB + woff);
                #pragma unroll
                for (int s = 0; s < 2; s++) {
                    int ks = kp * 2 + s;
                    mma16816(c[nt], ah[ks], wh[2*s], wh[2*s+1]);
                    mma16816(c[nt], ah[ks], wl[2*s], wl[2*s+1]);
                    mma16816(c[nt], al[ks], wh[2*s], wh[2*s+1]);
                }
            }
        }
    }

    if (which == 2) {
        #pragma unroll
        for (int nt = 0; nt < 4; nt++)
            #pragma unroll
            for (int h = 0; h < 2; h++) {
                int row = m0 + mw * 16 + g + 8 * h;
                int col = nw * 32 + nt * 8 + 2 * tig;
                g_Vht[(size_t)col * SEQ + row]       = __float2half_rn(c[nt][2*h]);
                g_Vht[(size_t)(col + 1) * SEQ + row] = __float2half_rn(c[nt][2*h+1]);
            }
    } else {
        __half* Hp = which ? g_Kh : g_Qh;
        __half* Lp = which ? g_Kl : g_Ql;
        #pragma unroll
        for (int nt = 0; nt < 4; nt++)
            #pragma unroll
            for (int h = 0; h < 2; h++) {
                int row = m0 + mw * 16 + g + 8 * h;
                float v0 = c[nt][2*h], v1 = c[nt][2*h+1];
                __half h0 = __float2half_rn(v0), h1 = __float2half_rn(v1);
                size_t base = (size_t)row * DK + nw * 32 + nt * 8 + 2 * tig;
                *(__half2*)&Hp[base] = __halves2half2(h0, h1);
                *(__half2*)&Lp[base] = __floats2half2_rn(v0 - __half2float(h0),
                                                         v1 - __half2float(h1));
            }
    }
}

// ---------------------------------------------------------------------------
// flash smem loaders (stride 144; 64-row tiles = 512 chunks = 2 iters)
// ---------------------------------------------------------------------------
__device__ __forceinline__ void load_k64(uint32_t dstbase, const __half* src, int n0, int tid){
    #pragma unroll
    for (int i = 0; i < 2; i++) {
        int f = i * 256 + tid;
        int row = f >> 3, c = f & 7;
        CP16(dstbase + (uint32_t)(row * FS + c * 16),
             src + (size_t)(n0 + row) * DK + c * 8);
    }
}
__device__ __forceinline__ void load_v64(uint32_t dstbase, const __half* src, int k0, int tid){
    #pragma unroll
    for (int i = 0; i < 2; i++) {
        int f = i * 256 + tid;
        int row = f >> 3, c = f & 7;
        CP16(dstbase + (uint32_t)(row * FS + c * 16),
             src + (size_t)row * SEQ + k0 + c * 8);
    }
}

// ---------------------------------------------------------------------------
// HMMA flash attention. grid = (SEQ/BM, NSPLIT) = (64, 4), 256 threads.
// ex2.approx.f16x2 softmax; l accumulated via MMA ones-column.
// ---------------------------------------------------------------------------
__global__ __launch_bounds__(256, 2) void flash_kernel()
{
    extern __shared__ char smem[];
    const uint32_t sb = smem_u32(smem);

    const int tid  = threadIdx.x;
    const int wid  = tid >> 5;
    const int lane = tid & 31;
    const int g    = lane >> 2;
    const int tig  = lane & 3;
    const int q0   = blockIdx.x * BM;
    const int split  = blockIdx.y;
    const int n_base = split * KV_PER;

    // prologue: Q (h+l) into smem + KV tile 0 into buf 0
    #pragma unroll
    for (int i = 0; i < 4; i++) {                 // Qh: 128 rows * 8 chunks
        int f = i * 256 + tid;
        int row = f >> 3, c = f & 7;
        uint32_t d = (uint32_t)(row * FS + c * 16);
        const size_t s = (size_t)(q0 + row) * DK + c * 8;
        CP16(sb + SM_QH + d, g_Qh + s);
        CP16(sb + SM_QL + d, g_Ql + s);
    }
    load_k64(sb + SM_KH, g_Kh, n_base, tid);
    load_k64(sb + SM_KL, g_Kl, n_base, tid);
    load_v64(sb + SM_V,  g_Vht, n_base, tid);
    CP_COMMIT();

    float O[8][4];
    #pragma unroll
    for (int d = 0; d < 8; d++)
        #pragma unroll
        for (int j = 0; j < 4; j++) O[d][j] = 0.0f;
    float lsum[4] = {0.f, 0.f, 0.f, 0.f};         // row-sum accumulator (P @ ones)
    float m_run[2] = {-1e30f, -1e30f};

    const uint32_t ONE2 = 0x3C003C00u;            // half2(1.0, 1.0)

    for (int t = 0; t < TILES; ++t) {
        CP_WAIT0();
        __syncthreads();

        const int buf = t & 1, nb = (t + 1) & 1;
        if (t + 1 < TILES) {
            int n1 = n_base + (t + 1) * BN;
            load_k64(sb + SM_KH + nb * FK_TB, g_Kh, n1, tid);
            load_k64(sb + SM_KL + nb * FK_TB, g_Kl, n1, tid);
            load_v64(sb + SM_V  + nb * FK_TB, g_Vht, n1, tid);
        }
        CP_COMMIT();

        // Q A-fragments reloaded from smem (keeps them transient)
        uint32_t aQh[4][4], aQl[4][4];
        #pragma unroll
        for (int ks = 0; ks < 4; ks++) {
            uint32_t aoff = (uint32_t)((wid * 16 + (lane & 15)) * FS
                                       + ks * 32 + (lane >> 4) * 16);
            ldsm4(aQh[ks], sb + SM_QH + aoff);
            ldsm4(aQl[ks], sb + SM_QL + aoff);
        }

        // S = Qh*Kh + Qh*Kl + Ql*Kh   (16 x 64 per warp)
        const uint32_t khb = sb + SM_KH + buf * FK_TB;
        const uint32_t klb = sb + SM_KL + buf * FK_TB;
        float c[8][4];
        #pragma unroll
        for (int nt = 0; nt < 8; nt++) {
            c[nt][0] = c[nt][1] = c[nt][2] = c[nt][3] = 0.0f;
            #pragma unroll
            for (int kp = 0; kp < 2; kp++) {
                uint32_t off = (uint32_t)((nt * 8 + (lane & 7)) * FS
                                          + kp * 64 + (lane >> 3) * 16);
                uint32_t bh[4], bl[4];
                ldsm4(bh, khb + off);
                ldsm4(bl, klb + off);
                #pragma unroll
                for (int s = 0; s < 2; s++) {
                    int ks = kp * 2 + s;
                    mma16816(c[nt], aQh[ks], bh[2*s], bh[2*s+1]);
                    mma16816(c[nt], aQh[ks], bl[2*s], bl[2*s+1]);
                    mma16816(c[nt], aQl[ks], bh[2*s], bh[2*s+1]);
                }
            }
        }

        // online max update (warp-local; rows g and g+8); rescale O and lsum
        float mL[2];
        #pragma unroll
        for (int h = 0; h < 2; h++) {
            float mt = -1e30f;
            #pragma unroll
            for (int nt = 0; nt < 8; nt++)
                mt = fmaxf(mt, fmaxf(c[nt][2*h], c[nt][2*h+1]));
            mt = fmaxf(mt, __shfl_xor_sync(0xffffffffu, mt, 1));
            mt = fmaxf(mt, __shfl_xor_sync(0xffffffffu, mt, 2));
            float mnew  = fmaxf(m_run[h], mt);
            float alpha = __expf(m_run[h] - mnew);
            m_run[h] = mnew;
            mL[h] = mnew * L2E;
            lsum[2*h]   *= alpha;
            lsum[2*h+1] *= alpha;
            #pragma unroll
            for (int d = 0; d < 8; d++) { O[d][2*h] *= alpha; O[d][2*h+1] *= alpha; }
        }

        // P = 2^(s*log2e - m*log2e) via ex2.approx.f16x2; result IS the A-frag
        uint32_t aP[4][4];
        #pragma unroll
        for (int nt = 0; nt < 8; nt++) {
            uint32_t pa = ex2h2(fmaf(c[nt][0], L2E, -mL[0]),
                                fmaf(c[nt][1], L2E, -mL[0]));
            uint32_t pb = ex2h2(fmaf(c[nt][2], L2E, -mL[1]),
                                fmaf(c[nt][3], L2E, -mL[1]));
            aP[nt >> 1][(nt & 1) * 2 + 0] = pa;
            aP[nt >> 1][(nt & 1) * 2 + 1] = pb;
        }

        // lsum += P @ ones  (constant B fragment, no smem)
        #pragma unroll
        for (int k2 = 0; k2 < 4; k2++)
            mma16816(lsum, aP[k2], ONE2, ONE2);

        // O += P @ Vh
        const uint32_t vhb = sb + SM_V + buf * FK_TB;
        #pragma unroll
        for (int dt = 0; dt < 8; dt++) {
            #pragma unroll
            for (int vp = 0; vp < 2; vp++) {
                uint32_t off = (uint32_t)((dt * 8 + (lane & 7)) * FS
                                          + vp * 64 + (lane >> 3) * 16);
                uint32_t vh[4];
                ldsm4(vh, vhb + off);
                #pragma unroll
                for (int s = 0; s < 2; s++) {
                    int k2 = vp * 2 + s;
                    mma16816(O[dt], aP[k2], vh[2*s], vh[2*s+1]);
                }
            }
        }
    }

    // epilogue: unnormalized partials + (m, l)
    #pragma unroll
    for (int h = 0; h < 2; h++) {
        int row = q0 + wid * 16 + g + 8 * h;
        size_t rb = ((size_t)split * SEQ + row) * DV;
        #pragma unroll
        for (int dt = 0; dt < 8; dt++) {
            float2 v = make_float2(O[dt][2*h], O[dt][2*h+1]);
            *(float2*)&g_Op[rb + dt * 8 + 2 * tig] = v;
        }
        if (tig == 0) {
            g_pm[split * SEQ + row] = m_run[h];
            g_pl[split * SEQ + row] = lsum[2*h];
        }
    }
}

// ---------------------------------------------------------------------------
// combine the NSPLIT KV-split partials
// ---------------------------------------------------------------------------
__global__ __launch_bounds__(256, 1) void combine_kernel(float* __restrict__ out)
{
    int idx = blockIdx.x * 256 + threadIdx.x;
    int row = idx >> 4;
    int c4  = (idx & 15) * 4;

    float m[NSPLIT];
    float M = -1e30f;
    #pragma unroll
    for (int j = 0; j < NSPLIT; j++) {
        m[j] = g_pm[j * SEQ + row];
        M = fmaxf(M, m[j]);
    }
    float w[NSPLIT];
    float l = 0.0f;
    #pragma unroll
    for (int j = 0; j < NSPLIT; j++) {
        w[j] = __expf(m[j] - M);
        l += w[j] * g_pl[j * SEQ + row];
    }
    float inv = 1.0f / l;

    float4 o = make_float4(0.f, 0.f, 0.f, 0.f);
    #pragma unroll
    for (int j = 0; j < NSPLIT; j++) {
        float4 a = *(const float4*)&g_Op[((size_t)j * SEQ + row) * DV + c4];
        o.x += w[j] * a.x; o.y += w[j] * a.y;
        o.z += w[j] * a.z; o.w += w[j] * a.w;
    }
    o.x *= inv; o.y *= inv; o.z *= inv; o.w *= inv;
    *(float4*)&out[(size_t)row * DV + c4] = o;
}

// ---------------------------------------------------------------------------
extern "C" void kernel_launch(void* const* d_in, const int* in_sizes, int n_in,
                              void* d_out, int out_size)
{
    const float* x  = (const float*)d_in[0];
    const float* Wq = (const float*)d_in[1];
    const float* Wk = (const float*)d_in[2];
    const float* Wv = (const float*)d_in[3];
    float* out = (float*)d_out;

    convert_x<<<SEQ * DIM / 1024, 256>>>(x);
    convert_w<<<dim3(3, 8), 256>>>(Wq, Wk, Wv);

    cudaFuncSetAttribute(hmma_qkv,
                         cudaFuncAttributeMaxDynamicSharedMemorySize, QK_SMEM);
    hmma_qkv<<<dim3(SEQ / 64, 3), 256, QK_SMEM>>>();

    cudaFuncSetAttribute(flash_kernel,
                         cudaFuncAttributeMaxDynamicSharedMemorySize, SM_TOTAL);
    flash_kernel<<<dim3(SEQ / BM, NSPLIT), 256, SM_TOTAL>>>();

    combine_kernel<<<SEQ * 16 / 256, 256>>>(out);
}

// round 13
// speedup vs baseline: 1.1394x; 1.1096x over previous
#include <cuda_runtime.h>
#include <cuda_fp16.h>
#include <cstdint>

#define SEQ 8192
#define DIM 512
#define DK  64
#define DV  64
#define BM  128
#define BN  64
#define NSPLIT 4
#define KV_PER (SEQ/NSPLIT)     // 2048
#define TILES  (KV_PER/BN)      // 32

// ---- flash smem (bytes): stride 144 everywhere ----
#define FS 144
#define FK_TB (64 * FS)              // 9216
#define SM_QH 0                      // 128 rows * 144 = 18432
#define SM_QL 18432
#define SM_KH 36864                  // 2 bufs * 9216
#define SM_KL (36864 + 18432)        // 55296
#define SM_V  (55296 + 18432)        // 73728, 2 bufs
#define SM_TOTAL (73728 + 18432)     // 92160

// ---- qkv smem (bytes): M-tile 64, k-chunk 64, stride 144 ----
#define QS 144
#define QK_TB (64 * QS)             // 9216 per split tile
#define QK_BUF (4 * QK_TB)          // xh, xl, wh, wl = 36864
#define QK_SMEM (2 * QK_BUF)        // 73728

#define L2E 1.4426950408889634f

// ---------------- global scratch ----------------
__device__ __half g_xh[SEQ*DIM], g_xl[SEQ*DIM];
__device__ __half g_Wth[3*DK*DIM], g_Wtl[3*DK*DIM];  // W^T [n][k], Q pre-scaled
__device__ __half g_Qh[SEQ*DK], g_Ql[SEQ*DK];
__device__ __half g_Kh[SEQ*DK], g_Kl[SEQ*DK];
__device__ __half g_Vht[DV*SEQ];                     // V^T fp16
__device__ float  g_Op[NSPLIT*SEQ*DV];
__device__ float  g_pm[NSPLIT*SEQ], g_pl[NSPLIT*SEQ];

// ---------------- helpers ----------------
__device__ __forceinline__ uint32_t smem_u32(const void* p){
    uint32_t a;
    asm("{ .reg .u64 t; cvta.to.shared.u64 t, %1; cvt.u32.u64 %0, t; }" : "=r"(a) : "l"(p));
    return a;
}
#define CP16(dst, src) asm volatile("cp.async.cg.shared.global [%0], [%1], 16;" :: "r"(dst), "l"(src) : "memory")
#define CP_COMMIT()    asm volatile("cp.async.commit_group;" ::: "memory")
#define CP_WAIT0()     asm volatile("cp.async.wait_group 0;" ::: "memory")

__device__ __forceinline__ void mma16816(float* c, const uint32_t* a, uint32_t b0, uint32_t b1){
    asm volatile("mma.sync.aligned.m16n8k16.row.col.f32.f16.f16.f32 "
        "{%0,%1,%2,%3}, {%4,%5,%6,%7}, {%8,%9}, {%0,%1,%2,%3};"
        : "+f"(c[0]), "+f"(c[1]), "+f"(c[2]), "+f"(c[3])
        : "r"(a[0]), "r"(a[1]), "r"(a[2]), "r"(a[3]), "r"(b0), "r"(b1));
}
__device__ __forceinline__ void ldsm4(uint32_t* r, uint32_t addr){
    asm volatile("ldmatrix.sync.aligned.m8n8.x4.shared.b16 {%0,%1,%2,%3}, [%4];"
        : "=r"(r[0]), "=r"(r[1]), "=r"(r[2]), "=r"(r[3]) : "r"(addr));
}
// pack two fp32 exponents (base-2) to half2 and exponentiate on MUFU.f16x2
__device__ __forceinline__ uint32_t ex2h2(float lo, float hi){
    __half2 h = __floats2half2_rn(lo, hi);
    uint32_t u = reinterpret_cast<uint32_t&>(h);
    uint32_t r;
    asm volatile("ex2.approx.f16x2 %0, %1;" : "=r"(r) : "r"(u));
    return r;
}

// ---------------------------------------------------------------------------
// Converts
// ---------------------------------------------------------------------------
__global__ __launch_bounds__(256, 1) void convert_x(const float* __restrict__ x)
{
    size_t i = ((size_t)blockIdx.x * 256 + threadIdx.x) * 4;
    float4 v = *(const float4*)(x + i);
    __half h0 = __float2half_rn(v.x), h1 = __float2half_rn(v.y);
    __half h2 = __float2half_rn(v.z), h3 = __float2half_rn(v.w);
    *(__half2*)&g_xh[i]   = __halves2half2(h0, h1);
    *(__half2*)&g_xh[i+2] = __halves2half2(h2, h3);
    *(__half2*)&g_xl[i]   = __floats2half2_rn(v.x - __half2float(h0), v.y - __half2float(h1));
    *(__half2*)&g_xl[i+2] = __floats2half2_rn(v.z - __half2float(h2), v.w - __half2float(h3));
}

__global__ __launch_bounds__(256, 1) void convert_w(
    const float* __restrict__ Wq, const float* __restrict__ Wk, const float* __restrict__ Wv)
{
    const int w = blockIdx.x;
    const float* W = (w == 0) ? Wq : (w == 1) ? Wk : Wv;
    const float sc = (w == 0) ? 0.125f : 1.0f;     // fold 1/sqrt(64) into Wq
    __half* Hh = g_Wth + (size_t)w * DK * DIM;
    __half* Hl = g_Wtl + (size_t)w * DK * DIM;
    int idx = blockIdx.y * 4096 + threadIdx.x;
    #pragma unroll
    for (int i = 0; i < 16; i++, idx += 256) {
        int k = idx / DK, n = idx % DK;
        float v = W[idx] * sc;
        __half h = __float2half_rn(v);
        Hh[(size_t)n * DIM + k] = h;
        Hl[(size_t)n * DIM + k] = __float2half_rn(v - __half2float(h));
    }
}

// ---------------------------------------------------------------------------
// HMMA QKV: C = x @ W, 3-term fp16 split. grid (SEQ/64, 3), 256 thr.
// ---------------------------------------------------------------------------
__global__ __launch_bounds__(256, 1) void hmma_qkv()
{
    extern __shared__ char smem[];
    const uint32_t sb = smem_u32(smem);
    const int tid = threadIdx.x, wid = tid >> 5, lane = tid & 31;
    const int g = lane >> 2, tig = lane & 3;
    const int mw = wid & 3;
    const int nw = wid >> 2;
    const int which = blockIdx.y;
    const int m0 = blockIdx.x * 64;
    const __half* Wh = g_Wth + (size_t)which * DK * DIM;
    const __half* Wl = g_Wtl + (size_t)which * DK * DIM;

    auto load_chunk = [&](int buf, int k0) {
        uint32_t base = sb + buf * QK_BUF;
        #pragma unroll
        for (int i = 0; i < 2; i++) {
            int f = i * 256 + tid;
            int row = f >> 3, c = f & 7;
            uint32_t d = (uint32_t)(row * QS + c * 16);
            const size_t s = (size_t)(m0 + row) * DIM + k0 + c * 8;
            CP16(base + d,         g_xh + s);
            CP16(base + QK_TB + d, g_xl + s);
        }
        #pragma unroll
        for (int i = 0; i < 2; i++) {
            int f = i * 256 + tid;
            int row = f >> 3, c = f & 7;
            uint32_t d = (uint32_t)(row * QS + c * 16);
            const size_t s = (size_t)row * DIM + k0 + c * 8;
            CP16(base + 2*QK_TB + d, Wh + s);
            CP16(base + 3*QK_TB + d, Wl + s);
        }
    };

    load_chunk(0, 0);
    CP_COMMIT();

    float c[4][4];
    #pragma unroll
    for (int nt = 0; nt < 4; nt++)
        c[nt][0] = c[nt][1] = c[nt][2] = c[nt][3] = 0.0f;

    for (int ch = 0; ch < 8; ch++) {
        CP_WAIT0();
        __syncthreads();
        if (ch < 7) { load_chunk((ch + 1) & 1, (ch + 1) * 64); CP_COMMIT(); }

        const uint32_t xb = sb + (ch & 1) * QK_BUF;

        uint32_t ah[4][4], al[4][4];
        #pragma unroll
        for (int ks = 0; ks < 4; ks++) {
            uint32_t aoff = (uint32_t)((mw * 16 + (lane & 15)) * QS
                                       + ks * 32 + (lane >> 4) * 16);
            ldsm4(ah[ks], xb + aoff);
            ldsm4(al[ks], xb + QK_TB + aoff);
        }
        #pragma unroll
        for (int nt = 0; nt < 4; nt++) {
            #pragma unroll
            for (int kp = 0; kp < 2; kp++) {
                uint32_t woff = (uint32_t)((nw * 32 + nt * 8 + (lane & 7)) * QS
                                           + kp * 64 + (lane >> 3) * 16);
                uint32_t wh[4], wl[4];
                ldsm4(wh, xb + 2*QK_TB + woff);
                ldsm4(wl, xb + 3*QK_TB + woff);
                #pragma unroll
                for (int s = 0; s < 2; s++) {
                    int ks = kp * 2 + s;
                    mma16816(c[nt], ah[ks], wh[2*s], wh[2*s+1]);
                    mma16816(c[nt], ah[ks], wl[2*s], wl[2*s+1]);
                    mma16816(c[nt], al[ks], wh[2*s], wh[2*s+1]);
                }
            }
        }
    }

    if (which == 2) {
        #pragma unroll
        for (int nt = 0; nt < 4; nt++)
            #pragma unroll
            for (int h = 0; h < 2; h++) {
                int row = m0 + mw * 16 + g + 8 * h;
                int col = nw * 32 + nt * 8 + 2 * tig;
                g_Vht[(size_t)col * SEQ + row]       = __float2half_rn(c[nt][2*h]);
                g_Vht[(size_t)(col + 1) * SEQ + row] = __float2half_rn(c[nt][2*h+1]);
            }
    } else {
        __half* Hp = which ? g_Kh : g_Qh;
        __half* Lp = which ? g_Kl : g_Ql;
        #pragma unroll
        for (int nt = 0; nt < 4; nt++)
            #pragma unroll
            for (int h = 0; h < 2; h++) {
                int row = m0 + mw * 16 + g + 8 * h;
                float v0 = c[nt][2*h], v1 = c[nt][2*h+1];
                __half h0 = __float2half_rn(v0), h1 = __float2half_rn(v1);
                size_t base = (size_t)row * DK + nw * 32 + nt * 8 + 2 * tig;
                *(__half2*)&Hp[base] = __halves2half2(h0, h1);
                *(__half2*)&Lp[base] = __floats2half2_rn(v0 - __half2float(h0),
                                                         v1 - __half2float(h1));
            }
    }
}

// ---------------------------------------------------------------------------
// flash smem loaders (128 threads; stride 144)
// ---------------------------------------------------------------------------
__device__ __forceinline__ void load_k64(uint32_t dstbase, const __half* src, int n0, int tid){
    #pragma unroll
    for (int i = 0; i < 4; i++) {
        int f = i * 128 + tid;
        int row = f >> 3, c = f & 7;
        CP16(dstbase + (uint32_t)(row * FS + c * 16),
             src + (size_t)(n0 + row) * DK + c * 8);
    }
}
__device__ __forceinline__ void load_v64(uint32_t dstbase, const __half* src, int k0, int tid){
    #pragma unroll
    for (int i = 0; i < 4; i++) {
        int f = i * 128 + tid;
        int row = f >> 3, c = f & 7;
        CP16(dstbase + (uint32_t)(row * FS + c * 16),
             src + (size_t)row * SEQ + k0 + c * 8);
    }
}

// ---------------------------------------------------------------------------
// HMMA flash attention, M=32 per warp. grid (SEQ/BM, NSPLIT) = (64,4),
// 128 threads (4 warps), 2 CTAs/SM. K/V fragments reused across 2 m-blocks.
// ---------------------------------------------------------------------------
__global__ __launch_bounds__(128, 2) void flash_kernel()
{
    extern __shared__ char smem[];
    const uint32_t sb = smem_u32(smem);

    const int tid  = threadIdx.x;
    const int wid  = tid >> 5;
    const int lane = tid & 31;
    const int g    = lane >> 2;
    const int tig  = lane & 3;
    const int q0   = blockIdx.x * BM;
    const int split  = blockIdx.y;
    const int n_base = split * KV_PER;

    // prologue: Q (h+l) into smem + KV tile 0 into buf 0
    #pragma unroll
    for (int i = 0; i < 8; i++) {                 // Q: 128 rows * 8 chunks
        int f = i * 128 + tid;
        int row = f >> 3, c = f & 7;
        uint32_t d = (uint32_t)(row * FS + c * 16);
        const size_t s = (size_t)(q0 + row) * DK + c * 8;
        CP16(sb + SM_QH + d, g_Qh + s);
        CP16(sb + SM_QL + d, g_Ql + s);
    }
    load_k64(sb + SM_KH, g_Kh, n_base, tid);
    load_k64(sb + SM_KL, g_Kl, n_base, tid);
    load_v64(sb + SM_V,  g_Vht, n_base, tid);
    CP_COMMIT();

    float O[2][8][4];
    #pragma unroll
    for (int m = 0; m < 2; m++)
        #pragma unroll
        for (int d = 0; d < 8; d++)
            #pragma unroll
            for (int j = 0; j < 4; j++) O[m][d][j] = 0.0f;
    float lsum[2][4] = {{0.f,0.f,0.f,0.f},{0.f,0.f,0.f,0.f}};
    float m_run[2][2] = {{-1e30f,-1e30f},{-1e30f,-1e30f}};

    const uint32_t ONE2 = 0x3C003C00u;            // half2(1.0, 1.0)

    for (int t = 0; t < TILES; ++t) {
        CP_WAIT0();
        __syncthreads();

        const int buf = t & 1, nb = (t + 1) & 1;
        if (t + 1 < TILES) {
            int n1 = n_base + (t + 1) * BN;
            load_k64(sb + SM_KH + nb * FK_TB, g_Kh, n1, tid);
            load_k64(sb + SM_KL + nb * FK_TB, g_Kl, n1, tid);
            load_v64(sb + SM_V  + nb * FK_TB, g_Vht, n1, tid);
        }
        CP_COMMIT();

        // S = Qh*Kh + Qh*Kl + Ql*Kh   (32 x 64 per warp; K frags shared
        // across the two 16-row m-blocks)
        const uint32_t khb = sb + SM_KH + buf * FK_TB;
        const uint32_t klb = sb + SM_KL + buf * FK_TB;
        float c[2][8][4];
        #pragma unroll
        for (int m = 0; m < 2; m++)
            #pragma unroll
            for (int nt = 0; nt < 8; nt++)
                c[m][nt][0] = c[m][nt][1] = c[m][nt][2] = c[m][nt][3] = 0.0f;

        #pragma unroll
        for (int kp = 0; kp < 2; kp++) {
            uint32_t qh[2][2][4], ql[2][2][4];    // [m][s][4], transient
            #pragma unroll
            for (int m = 0; m < 2; m++)
                #pragma unroll
                for (int s = 0; s < 2; s++) {
                    uint32_t aoff = (uint32_t)((wid * 32 + m * 16 + (lane & 15)) * FS
                                               + (kp * 2 + s) * 32 + (lane >> 4) * 16);
                    ldsm4(qh[m][s], sb + SM_QH + aoff);
                    ldsm4(ql[m][s], sb + SM_QL + aoff);
                }
            #pragma unroll
            for (int nt = 0; nt < 8; nt++) {
                uint32_t off = (uint32_t)((nt * 8 + (lane & 7)) * FS
                                          + kp * 64 + (lane >> 3) * 16);
                uint32_t bh[4], bl[4];
                ldsm4(bh, khb + off);
                ldsm4(bl, klb + off);
                #pragma unroll
                for (int m = 0; m < 2; m++)
                    #pragma unroll
                    for (int s = 0; s < 2; s++) {
                        mma16816(c[m][nt], qh[m][s], bh[2*s], bh[2*s+1]);
                        mma16816(c[m][nt], qh[m][s], bl[2*s], bl[2*s+1]);
                        mma16816(c[m][nt], ql[m][s], bh[2*s], bh[2*s+1]);
                    }
            }
        }

        // online max update (warp-local); rescale O and lsum
        float mL[2][2];
        #pragma unroll
        for (int m = 0; m < 2; m++)
            #pragma unroll
            for (int h = 0; h < 2; h++) {
                float mt = -1e30f;
                #pragma unroll
                for (int nt = 0; nt < 8; nt++)
                    mt = fmaxf(mt, fmaxf(c[m][nt][2*h], c[m][nt][2*h+1]));
                mt = fmaxf(mt, __shfl_xor_sync(0xffffffffu, mt, 1));
                mt = fmaxf(mt, __shfl_xor_sync(0xffffffffu, mt, 2));
                float mnew  = fmaxf(m_run[m][h], mt);
                float alpha = __expf(m_run[m][h] - mnew);
                m_run[m][h] = mnew;
                mL[m][h] = mnew * L2E;
                lsum[m][2*h]   *= alpha;
                lsum[m][2*h+1] *= alpha;
                #pragma unroll
                for (int d = 0; d < 8; d++) {
                    O[m][d][2*h]   *= alpha;
                    O[m][d][2*h+1] *= alpha;
                }
            }

        // P = 2^(s*log2e - m*log2e) via ex2.approx.f16x2; result IS the A-frag
        uint32_t aP[2][4][4];
        #pragma unroll
        for (int m = 0; m < 2; m++)
            #pragma unroll
            for (int nt = 0; nt < 8; nt++) {
                uint32_t pa = ex2h2(fmaf(c[m][nt][0], L2E, -mL[m][0]),
                                    fmaf(c[m][nt][1], L2E, -mL[m][0]));
                uint32_t pb = ex2h2(fmaf(c[m][nt][2], L2E, -mL[m][1]),
                                    fmaf(c[m][nt][3], L2E, -mL[m][1]));
                aP[m][nt >> 1][(nt & 1) * 2 + 0] = pa;
                aP[m][nt >> 1][(nt & 1) * 2 + 1] = pb;
            }

        // lsum += P @ ones  (constant B fragment, no smem)
        #pragma unroll
        for (int m = 0; m < 2; m++)
            #pragma unroll
            for (int k2 = 0; k2 < 4; k2++)
                mma16816(lsum[m], aP[m][k2], ONE2, ONE2);

        // O += P @ Vh   (V frags shared across m-blocks)
        const uint32_t vhb = sb + SM_V + buf * FK_TB;
        #pragma unroll
        for (int dt = 0; dt < 8; dt++) {
            #pragma unroll
            for (int vp = 0; vp < 2; vp++) {
                uint32_t off = (uint32_t)((dt * 8 + (lane & 7)) * FS
                                          + vp * 64 + (lane >> 3) * 16);
                uint32_t vh[4];
                ldsm4(vh, vhb + off);
                #pragma unroll
                for (int m = 0; m < 2; m++)
                    #pragma unroll
                    for (int s = 0; s < 2; s++) {
                        int k2 = vp * 2 + s;
                        mma16816(O[m][dt], aP[m][k2], vh[2*s], vh[2*s+1]);
                    }
            }
        }
    }

    // epilogue: unnormalized partials + (m, l)
    #pragma unroll
    for (int m = 0; m < 2; m++)
        #pragma unroll
        for (int h = 0; h < 2; h++) {
            int row = q0 + wid * 32 + m * 16 + g + 8 * h;
            size_t rb = ((size_t)split * SEQ + row) * DV;
            #pragma unroll
            for (int dt = 0; dt < 8; dt++) {
                float2 v = make_float2(O[m][dt][2*h], O[m][dt][2*h+1]);
                *(float2*)&g_Op[rb + dt * 8 + 2 * tig] = v;
            }
            if (tig == 0) {
                g_pm[split * SEQ + row] = m_run[m][h];
                g_pl[split * SEQ + row] = lsum[m][2*h];
            }
        }
}

// ---------------------------------------------------------------------------
// combine the NSPLIT KV-split partials
// ---------------------------------------------------------------------------
__global__ __launch_bounds__(256, 1) void combine_kernel(float* __restrict__ out)
{
    int idx = blockIdx.x * 256 + threadIdx.x;
    int row = idx >> 4;
    int c4  = (idx & 15) * 4;

    float m[NSPLIT];
    float M = -1e30f;
    #pragma unroll
    for (int j = 0; j < NSPLIT; j++) {
        m[j] = g_pm[j * SEQ + row];
        M = fmaxf(M, m[j]);
    }
    float w[NSPLIT];
    float l = 0.0f;
    #pragma unroll
    for (int j = 0; j < NSPLIT; j++) {
        w[j] = __expf(m[j] - M);
        l += w[j] * g_pl[j * SEQ + row];
    }
    float inv = 1.0f / l;

    float4 o = make_float4(0.f, 0.f, 0.f, 0.f);
    #pragma unroll
    for (int j = 0; j < NSPLIT; j++) {
        float4 a = *(const float4*)&g_Op[((size_t)j * SEQ + row) * DV + c4];
        o.x += w[j] * a.x; o.y += w[j] * a.y;
        o.z += w[j] * a.z; o.w += w[j] * a.w;
    }
    o.x *= inv; o.y *= inv; o.z *= inv; o.w *= inv;
    *(float4*)&out[(size_t)row * DV + c4] = o;
}

// ---------------------------------------------------------------------------
extern "C" void kernel_launch(void* const* d_in, const int* in_sizes, int n_in,
                              void* d_out, int out_size)
{
    const float* x  = (const float*)d_in[0];
    const float* Wq = (const float*)d_in[1];
    const float* Wk = (const float*)d_in[2];
    const float* Wv = (const float*)d_in[3];
    float* out = (float*)d_out;

    convert_x<<<SEQ * DIM / 1024, 256>>>(x);
    convert_w<<<dim3(3, 8), 256>>>(Wq, Wk, Wv);

    cudaFuncSetAttribute(hmma_qkv,
                         cudaFuncAttributeMaxDynamicSharedMemorySize, QK_SMEM);
    hmma_qkv<<<dim3(SEQ / 64, 3), 256, QK_SMEM>>>();

    cudaFuncSetAttribute(flash_kernel,
                         cudaFuncAttributeMaxDynamicSharedMemorySize, SM_TOTAL);
    flash_kernel<<<dim3(SEQ / BM, NSPLIT), 128, SM_TOTAL>>>();

    combine_kernel<<<SEQ * 16 / 256, 256>>>(out);
}

// round 15
// speedup vs baseline: 1.1865x; 1.0413x over previous
#include <cuda_runtime.h>
#include <cuda_fp16.h>
#include <cstdint>

#define SEQ 8192
#define DIM 512
#define DK  64
#define DV  64
#define BM  128
#define BN  64
#define NSPLIT 4
#define KV_PER (SEQ/NSPLIT)     // 2048
#define TILES  (KV_PER/BN)      // 32

// ---- flash smem (bytes): stride 144 everywhere ----
#define FS 144
#define FK_TB (64 * FS)              // 9216
#define SM_QH 0                      // 128 rows * 144 = 18432
#define SM_QL 18432
#define SM_KH 36864                  // 2 bufs * 9216
#define SM_KL (36864 + 18432)        // 55296
#define SM_V  (55296 + 18432)        // 73728, 2 bufs
#define SM_TOTAL (73728 + 18432)     // 92160

// ---- qkv smem (bytes): M-tile 64, k-chunk 64, stride 144 ----
#define QS 144
#define QK_TB (64 * QS)             // 9216 per split tile
#define QK_BUF (4 * QK_TB)          // xh, xl, wh, wl = 36864
#define QK_SMEM (2 * QK_BUF)        // 73728

#define L2E 1.4426950408889634f

// ---------------- global scratch ----------------
__device__ __half g_Wth[3*DK*DIM], g_Wtl[3*DK*DIM];  // W^T [n][k], Q pre-scaled
__device__ __half g_Qh[SEQ*DK], g_Ql[SEQ*DK];
__device__ __half g_Kh[SEQ*DK], g_Kl[SEQ*DK];
__device__ __half g_Vht[DV*SEQ];                     // V^T fp16
__device__ float  g_Op[NSPLIT*SEQ*DV];
__device__ float  g_pm[NSPLIT*SEQ], g_pl[NSPLIT*SEQ];

// ---------------- helpers ----------------
__device__ __forceinline__ uint32_t smem_u32(const void* p){
    uint32_t a;
    asm("{ .reg .u64 t; cvta.to.shared.u64 t, %1; cvt.u32.u64 %0, t; }" : "=r"(a) : "l"(p));
    return a;
}
#define CP16(dst, src) asm volatile("cp.async.cg.shared.global [%0], [%1], 16;" :: "r"(dst), "l"(src) : "memory")
#define CP_COMMIT()    asm volatile("cp.async.commit_group;" ::: "memory")
#define CP_WAIT0()     asm volatile("cp.async.wait_group 0;" ::: "memory")

__device__ __forceinline__ void mma16816(float* c, const uint32_t* a, uint32_t b0, uint32_t b1){
    asm volatile("mma.sync.aligned.m16n8k16.row.col.f32.f16.f16.f32 "
        "{%0,%1,%2,%3}, {%4,%5,%6,%7}, {%8,%9}, {%0,%1,%2,%3};"
        : "+f"(c[0]), "+f"(c[1]), "+f"(c[2]), "+f"(c[3])
        : "r"(a[0]), "r"(a[1]), "r"(a[2]), "r"(a[3]), "r"(b0), "r"(b1));
}
__device__ __forceinline__ void ldsm4(uint32_t* r, uint32_t addr){
    asm volatile("ldmatrix.sync.aligned.m8n8.x4.shared.b16 {%0,%1,%2,%3}, [%4];"
        : "=r"(r[0]), "=r"(r[1]), "=r"(r[2]), "=r"(r[3]) : "r"(addr));
}
// pack two fp32 exponents (base-2) to half2 and exponentiate on MUFU.f16x2
__device__ __forceinline__ uint32_t ex2h2(float lo, float hi){
    __half2 h = __floats2half2_rn(lo, hi);
    uint32_t u = reinterpret_cast<uint32_t&>(h);
    uint32_t r;
    asm volatile("ex2.approx.f16x2 %0, %1;" : "=r"(r) : "r"(u));
    return r;
}
#define STS8(addr, v) asm volatile("st.shared.v2.u32 [%0], {%1, %2};" :: "r"(addr), "r"(v.x), "r"(v.y) : "memory")

// ---------------------------------------------------------------------------
// convert_w: W -> W^T fp16 hi/lo (Q scale folded). grid (3, 8).
// ---------------------------------------------------------------------------
__global__ __launch_bounds__(256, 1) void convert_w(
    const float* __restrict__ Wq, const float* __restrict__ Wk, const float* __restrict__ Wv)
{
    const int w = blockIdx.x;
    const float* W = (w == 0) ? Wq : (w == 1) ? Wk : Wv;
    const float sc = (w == 0) ? 0.125f : 1.0f;     // fold 1/sqrt(64) into Wq
    __half* Hh = g_Wth + (size_t)w * DK * DIM;
    __half* Hl = g_Wtl + (size_t)w * DK * DIM;
    int idx = blockIdx.y * 4096 + threadIdx.x;
    #pragma unroll
    for (int i = 0; i < 16; i++, idx += 256) {
        int k = idx / DK, n = idx % DK;
        float v = W[idx] * sc;
        __half h = __float2half_rn(v);
        Hh[(size_t)n * DIM + k] = h;
        Hl[(size_t)n * DIM + k] = __float2half_rn(v - __half2float(h));
    }
}

// ---------------------------------------------------------------------------
// HMMA QKV v3: C = x @ W, 3-term fp16 split, x converted IN-KERNEL.
// grid (SEQ/64, 3), 256 thr. fp32 x LDGs software-pipelined one chunk ahead.
// ---------------------------------------------------------------------------
__global__ __launch_bounds__(256, 1) void hmma_qkv(const float* __restrict__ x)
{
    extern __shared__ char smem[];
    const uint32_t sb = smem_u32(smem);
    const int tid = threadIdx.x, wid = tid >> 5, lane = tid & 31;
    const int g = lane >> 2, tig = lane & 3;
    const int mw = wid & 3;
    const int nw = wid >> 2;
    const int which = blockIdx.y;
    const int m0 = blockIdx.x * 64;
    const __half* Wh = g_Wth + (size_t)which * DK * DIM;
    const __half* Wl = g_Wtl + (size_t)which * DK * DIM;

    // x chunk: 64 rows x 64 k fp32 = 1024 float4; 4 per thread.
    // f = i*256+tid; row = f>>4 (16 float4 per row); c4 = f&15.
    auto ldg_x = [&](float4* xr, int k0) {
        #pragma unroll
        for (int i = 0; i < 4; i++) {
            int f = i * 256 + tid;
            int row = f >> 4, c4 = f & 15;
            xr[i] = *(const float4*)(x + (size_t)(m0 + row) * DIM + k0 + c4 * 4);
        }
    };
    // convert + store to xh/xl tiles of buf
    auto sts_x = [&](const float4* xr, int buf) {
        uint32_t base = sb + buf * QK_BUF;
        #pragma unroll
        for (int i = 0; i < 4; i++) {
            int f = i * 256 + tid;
            int row = f >> 4, c4 = f & 15;
            float4 v = xr[i];
            __half h0 = __float2half_rn(v.x), h1 = __float2half_rn(v.y);
            __half h2 = __float2half_rn(v.z), h3 = __float2half_rn(v.w);
            uint2 hi, lo;
            __half2 a = __halves2half2(h0, h1), b = __halves2half2(h2, h3);
            hi.x = reinterpret_cast<uint32_t&>(a);
            hi.y = reinterpret_cast<uint32_t&>(b);
            __half2 la = __floats2half2_rn(v.x - __half2float(h0), v.y - __half2float(h1));
            __half2 lb = __floats2half2_rn(v.z - __half2float(h2), v.w - __half2float(h3));
            lo.x = reinterpret_cast<uint32_t&>(la);
            lo.y = reinterpret_cast<uint32_t&>(lb);
            uint32_t d = (uint32_t)(row * QS + c4 * 8);
            STS8(base + d, hi);
            STS8(base + QK_TB + d, lo);
        }
    };
    // W tiles via cp.async from pre-converted splits
    auto load_w = [&](int buf, int k0) {
        uint32_t base = sb + buf * QK_BUF;
        #pragma unroll
        for (int i = 0; i < 2; i++) {
            int f = i * 256 + tid;
            int row = f >> 3, c = f & 7;
            uint32_t d = (uint32_t)(row * QS + c * 16);
            const size_t s = (size_t)row * DIM + k0 + c * 8;
            CP16(base + 2*QK_TB + d, Wh + s);
            CP16(base + 3*QK_TB + d, Wl + s);
        }
    };

    // prologue: chunk 0
    {
        float4 x0[4];
        ldg_x(x0, 0);
        sts_x(x0, 0);
        load_w(0, 0);
        CP_COMMIT();
    }

    float c[4][4];
    #pragma unroll
    for (int nt = 0; nt < 4; nt++)
        c[nt][0] = c[nt][1] = c[nt][2] = c[nt][3] = 0.0f;

    float4 xr[4];
    for (int ch = 0; ch < 8; ch++) {
        if (ch < 7) ldg_x(xr, (ch + 1) * 64);   // issue early; consumed post-MMA
        CP_WAIT0();
        __syncthreads();

        const uint32_t xb = sb + (ch & 1) * QK_BUF;

        uint32_t ah[4][4], al[4][4];
        #pragma unroll
        for (int ks = 0; ks < 4; ks++) {
            uint32_t aoff = (uint32_t)((mw * 16 + (lane & 15)) * QS
                                       + ks * 32 + (lane >> 4) * 16);
            ldsm4(ah[ks], xb + aoff);
            ldsm4(al[ks], xb + QK_TB + aoff);
        }
        #pragma unroll
        for (int nt = 0; nt < 4; nt++) {
            #pragma unroll
            for (int kp = 0; kp < 2; kp++) {
                uint32_t woff = (uint32_t)((nw * 32 + nt * 8 + (lane & 7)) * QS
                                           + kp * 64 + (lane >> 3) * 16);
                uint32_t wh[4], wl[4];
                ldsm4(wh, xb + 2*QK_TB + woff);
                ldsm4(wl, xb + 3*QK_TB + woff);
                #pragma unroll
                for (int s = 0; s < 2; s++) {
                    int ks = kp * 2 + s;
                    mma16816(c[nt], ah[ks], wh[2*s], wh[2*s+1]);
                    mma16816(c[nt], ah[ks], wl[2*s], wl[2*s+1]);
                    mma16816(c[nt], al[ks], wh[2*s], wh[2*s+1]);
                }
            }
        }

        if (ch < 7) {
            sts_x(xr, (ch + 1) & 1);            // opposite buffer; safe past sync
            load_w((ch + 1) & 1, (ch + 1) * 64);
            CP_COMMIT();
        }
    }

    if (which == 2) {
        #pragma unroll
        for (int nt = 0; nt < 4; nt++)
            #pragma unroll
            for (int h = 0; h < 2; h++) {
                int row = m0 + mw * 16 + g + 8 * h;
                int col = nw * 32 + nt * 8 + 2 * tig;
                g_Vht[(size_t)col * SEQ + row]       = __float2half_rn(c[nt][2*h]);
                g_Vht[(size_t)(col + 1) * SEQ + row] = __float2half_rn(c[nt][2*h+1]);
            }
    } else {
        __half* Hp = which ? g_Kh : g_Qh;
        __half* Lp = which ? g_Kl : g_Ql;
        #pragma unroll
        for (int nt = 0; nt < 4; nt++)
            #pragma unroll
            for (int h = 0; h < 2; h++) {
                int row = m0 + mw * 16 + g + 8 * h;
                float v0 = c[nt][2*h], v1 = c[nt][2*h+1];
                __half h0 = __float2half_rn(v0), h1 = __float2half_rn(v1);
                size_t base = (size_t)row * DK + nw * 32 + nt * 8 + 2 * tig;
                *(__half2*)&Hp[base] = __halves2half2(h0, h1);
                *(__half2*)&Lp[base] = __floats2half2_rn(v0 - __half2float(h0),
                                                         v1 - __half2float(h1));
            }
    }
}

// ---------------------------------------------------------------------------
// flash smem loaders (128 threads; stride 144)
// ---------------------------------------------------------------------------
__device__ __forceinline__ void load_k64(uint32_t dstbase, const __half* src, int n0, int tid){
    #pragma unroll
    for (int i = 0; i < 4; i++) {
        int f = i * 128 + tid;
        int row = f >> 3, c = f & 7;
        CP16(dstbase + (uint32_t)(row * FS + c * 16),
             src + (size_t)(n0 + row) * DK + c * 8);
    }
}
__device__ __forceinline__ void load_v64(uint32_t dstbase, const __half* src, int k0, int tid){
    #pragma unroll
    for (int i = 0; i < 4; i++) {
        int f = i * 128 + tid;
        int row = f >> 3, c = f & 7;
        CP16(dstbase + (uint32_t)(row * FS + c * 16),
             src + (size_t)row * SEQ + k0 + c * 8);
    }
}

// ---------------------------------------------------------------------------
// HMMA flash attention, M=32 per warp. grid (SEQ/BM, NSPLIT) = (64,4),
// 128 threads (4 warps), 2 CTAs/SM. K/V fragments reused across 2 m-blocks.
// (unchanged from R13 winner)
// ---------------------------------------------------------------------------
__global__ __launch_bounds__(128, 2) void flash_kernel()
{
    extern __shared__ char smem[];
    const uint32_t sb = smem_u32(smem);

    const int tid  = threadIdx.x;
    const int wid  = tid >> 5;
    const int lane = tid & 31;
    const int g    = lane >> 2;
    const int tig  = lane & 3;
    const int q0   = blockIdx.x * BM;
    const int split  = blockIdx.y;
    const int n_base = split * KV_PER;

    #pragma unroll
    for (int i = 0; i < 8; i++) {                 // Q: 128 rows * 8 chunks
        int f = i * 128 + tid;
        int row = f >> 3, c = f & 7;
        uint32_t d = (uint32_t)(row * FS + c * 16);
        const size_t s = (size_t)(q0 + row) * DK + c * 8;
        CP16(sb + SM_QH + d, g_Qh + s);
        CP16(sb + SM_QL + d, g_Ql + s);
    }
    load_k64(sb + SM_KH, g_Kh, n_base, tid);
    load_k64(sb + SM_KL, g_Kl, n_base, tid);
    load_v64(sb + SM_V,  g_Vht, n_base, tid);
    CP_COMMIT();

    float O[2][8][4];
    #pragma unroll
    for (int m = 0; m < 2; m++)
        #pragma unroll
        for (int d = 0; d < 8; d++)
            #pragma unroll
            for (int j = 0; j < 4; j++) O[m][d][j] = 0.0f;
    float lsum[2][4] = {{0.f,0.f,0.f,0.f},{0.f,0.f,0.f,0.f}};
    float m_run[2][2] = {{-1e30f,-1e30f},{-1e30f,-1e30f}};

    const uint32_t ONE2 = 0x3C003C00u;            // half2(1.0, 1.0)

    for (int t = 0; t < TILES; ++t) {
        CP_WAIT0();
        __syncthreads();

        const int buf = t & 1, nb = (t + 1) & 1;
        if (t + 1 < TILES) {
            int n1 = n_base + (t + 1) * BN;
            load_k64(sb + SM_KH + nb * FK_TB, g_Kh, n1, tid);
            load_k64(sb + SM_KL + nb * FK_TB, g_Kl, n1, tid);
            load_v64(sb + SM_V  + nb * FK_TB, g_Vht, n1, tid);
        }
        CP_COMMIT();

        const uint32_t khb = sb + SM_KH + buf * FK_TB;
        const uint32_t klb = sb + SM_KL + buf * FK_TB;
        float c[2][8][4];
        #pragma unroll
        for (int m = 0; m < 2; m++)
            #pragma unroll
            for (int nt = 0; nt < 8; nt++)
                c[m][nt][0] = c[m][nt][1] = c[m][nt][2] = c[m][nt][3] = 0.0f;

        #pragma unroll
        for (int kp = 0; kp < 2; kp++) {
            uint32_t qh[2][2][4], ql[2][2][4];    // [m][s][4], transient
            #pragma unroll
            for (int m = 0; m < 2; m++)
                #pragma unroll
                for (int s = 0; s < 2; s++) {
                    uint32_t aoff = (uint32_t)((wid * 32 + m * 16 + (lane & 15)) * FS
                                               + (kp * 2 + s) * 32 + (lane >> 4) * 16);
                    ldsm4(qh[m][s], sb + SM_QH + aoff);
                    ldsm4(ql[m][s], sb + SM_QL + aoff);
                }
            #pragma unroll
            for (int nt = 0; nt < 8; nt++) {
                uint32_t off = (uint32_t)((nt * 8 + (lane & 7)) * FS
                                          + kp * 64 + (lane >> 3) * 16);
                uint32_t bh[4], bl[4];
                ldsm4(bh, khb + off);
                ldsm4(bl, klb + off);
                #pragma unroll
                for (int m = 0; m < 2; m++)
                    #pragma unroll
                    for (int s = 0; s < 2; s++) {
                        mma16816(c[m][nt], qh[m][s], bh[2*s], bh[2*s+1]);
                        mma16816(c[m][nt], qh[m][s], bl[2*s], bl[2*s+1]);
                        mma16816(c[m][nt], ql[m][s], bh[2*s], bh[2*s+1]);
                    }
            }
        }

        float mL[2][2];
        #pragma unroll
        for (int m = 0; m < 2; m++)
            #pragma unroll
            for (int h = 0; h < 2; h++) {
                float mt = -1e30f;
                #pragma unroll
                for (int nt = 0; nt < 8; nt++)
                    mt = fmaxf(mt, fmaxf(c[m][nt][2*h], c[m][nt][2*h+1]));
                mt = fmaxf(mt, __shfl_xor_sync(0xffffffffu, mt, 1));
                mt = fmaxf(mt, __shfl_xor_sync(0xffffffffu, mt, 2));
                float mnew  = fmaxf(m_run[m][h], mt);
                float alpha = __expf(m_run[m][h] - mnew);
                m_run[m][h] = mnew;
                mL[m][h] = mnew * L2E;
                lsum[m][2*h]   *= alpha;
                lsum[m][2*h+1] *= alpha;
                #pragma unroll
                for (int d = 0; d < 8; d++) {
                    O[m][d][2*h]   *= alpha;
                    O[m][d][2*h+1] *= alpha;
                }
            }

        uint32_t aP[2][4][4];
        #pragma unroll
        for (int m = 0; m < 2; m++)
            #pragma unroll
            for (int nt = 0; nt < 8; nt++) {
                uint32_t pa = ex2h2(fmaf(c[m][nt][0], L2E, -mL[m][0]),
                                    fmaf(c[m][nt][1], L2E, -mL[m][0]));
                uint32_t pb = ex2h2(fmaf(c[m][nt][2], L2E, -mL[m][1]),
                                    fmaf(c[m][nt][3], L2E, -mL[m][1]));
                aP[m][nt >> 1][(nt & 1) * 2 + 0] = pa;
                aP[m][nt >> 1][(nt & 1) * 2 + 1] = pb;
            }

        #pragma unroll
        for (int m = 0; m < 2; m++)
            #pragma unroll
            for (int k2 = 0; k2 < 4; k2++)
                mma16816(lsum[m], aP[m][k2], ONE2, ONE2);

        const uint32_t vhb = sb + SM_V + buf * FK_TB;
        #pragma unroll
        for (int dt = 0; dt < 8; dt++) {
            #pragma unroll
            for (int vp = 0; vp < 2; vp++) {
                uint32_t off = (uint32_t)((dt * 8 + (lane & 7)) * FS
                                          + vp * 64 + (lane >> 3) * 16);
                uint32_t vh[4];
                ldsm4(vh, vhb + off);
                #pragma unroll
                for (int m = 0; m < 2; m++)
                    #pragma unroll
                    for (int s = 0; s < 2; s++) {
                        int k2 = vp * 2 + s;
                        mma16816(O[m][dt], aP[m][k2], vh[2*s], vh[2*s+1]);
                    }
            }
        }
    }

    #pragma unroll
    for (int m = 0; m < 2; m++)
        #pragma unroll
        for (int h = 0; h < 2; h++) {
            int row = q0 + wid * 32 + m * 16 + g + 8 * h;
            size_t rb = ((size_t)split * SEQ + row) * DV;
            #pragma unroll
            for (int dt = 0; dt < 8; dt++) {
                float2 v = make_float2(O[m][dt][2*h], O[m][dt][2*h+1]);
                *(float2*)&g_Op[rb + dt * 8 + 2 * tig] = v;
            }
            if (tig == 0) {
                g_pm[split * SEQ + row] = m_run[m][h];
                g_pl[split * SEQ + row] = lsum[m][2*h];
            }
        }
}

// ---------------------------------------------------------------------------
// combine the NSPLIT KV-split partials
// ---------------------------------------------------------------------------
__global__ __launch_bounds__(256, 1) void combine_kernel(float* __restrict__ out)
{
    int idx = blockIdx.x * 256 + threadIdx.x;
    int row = idx >> 4;
    int c4  = (idx & 15) * 4;

    float m[NSPLIT];
    float M = -1e30f;
    #pragma unroll
    for (int j = 0; j < NSPLIT; j++) {
        m[j] = g_pm[j * SEQ + row];
        M = fmaxf(M, m[j]);
    }
    float w[NSPLIT];
    float l = 0.0f;
    #pragma unroll
    for (int j = 0; j < NSPLIT; j++) {
        w[j] = __expf(m[j] - M);
        l += w[j] * g_pl[j * SEQ + row];
    }
    float inv = 1.0f / l;

    float4 o = make_float4(0.f, 0.f, 0.f, 0.f);
    #pragma unroll
    for (int j = 0; j < NSPLIT; j++) {
        float4 a = *(const float4*)&g_Op[((size_t)j * SEQ + row) * DV + c4];
        o.x += w[j] * a.x; o.y += w[j] * a.y;
        o.z += w[j] * a.z; o.w += w[j] * a.w;
    }
    o.x *= inv; o.y *= inv; o.z *= inv; o.w *= inv;
    *(float4*)&out[(size_t)row * DV + c4] = o;
}

// ---------------------------------------------------------------------------
extern "C" void kernel_launch(void* const* d_in, const int* in_sizes, int n_in,
                              void* d_out, int out_size)
{
    const float* x  = (const float*)d_in[0];
    const float* Wq = (const float*)d_in[1];
    const float* Wk = (const float*)d_in[2];
    const float* Wv = (const float*)d_in[3];
    float* out = (float*)d_out;

    convert_w<<<dim3(3, 8), 256>>>(Wq, Wk, Wv);

    cudaFuncSetAttribute(hmma_qkv,
                         cudaFuncAttributeMaxDynamicSharedMemorySize, QK_SMEM);
    hmma_qkv<<<dim3(SEQ / 64, 3), 256, QK_SMEM>>>(x);

    cudaFuncSetAttribute(flash_kernel,
                         cudaFuncAttributeMaxDynamicSharedMemorySize, SM_TOTAL);
    flash_kernel<<<dim3(SEQ / BM, NSPLIT), 128, SM_TOTAL>>>();

    combine_kernel<<<SEQ * 16 / 256, 256>>>(out);
}